// round 11
// baseline (speedup 1.0000x reference)
#include <cuda_runtime.h>
#include <math.h>

#define NSEG    2047
#define NPIX    16384
#define NTILE   256          // 16 x 16 tiles of 8x8 px
#define NCAP    768          // smem candidate capacity
#define GAMMA4  800.0f       // gamma * 4 (raw-space d^2 = true d^2 / 4)
#define STEPR   (1.0f / 127.0f)            // raw-space grid step
// tile = 8x8 px, center (+3.5,+3.5): 2*half-diag = 7*sqrt(2) px (raw units)
#define THR_ADD (9.899495f * STEPR + 5e-4f)
#define FINF    __int_as_float(0x7F800000)

__device__ __forceinline__ float satmul(float a, float b) {
    float r; asm("mul.rn.sat.f32 %0,%1,%2;" : "=f"(r) : "f"(a), "f"(b)); return r;
}

// Cross-CTA state, reset by the last loss-CTA every run (graph-replay safe).
__device__ float    g_pix[2][NPIX];   // raw-space per-pixel min d^2
__device__ int      g_tile_cnt[NTILE];
__device__ float    g_loss = 0.0f;
__device__ unsigned g_done = 0;

// ---------------------------------------------------------------------------
// grid 512 x 256: bid = w*256 + swizzled tile (8x8 px). RAW [0,1] space.
// Phase 1: thread owns 8 contiguous segments; 7 coalesced LDG.128 stage its
//          28 floats; center eval from registers; block-min U; exact
//          triangle-inequality cull; survivors -> s_seg/s_inv from registers.
// Phase 2: warp = pixel row, lane = candidate slice (32); clamp-tail loop
//          (no padding, no extra barriers), unroll x2; warp shuffle-min merge.
// Pairing: publish 64 mins to g_pix; second arriver computes tile loss with
//          beta = exp(-800 * d2_raw); 256th loss-CTA writes out[0], resets.
// ---------------------------------------------------------------------------
__global__ void __launch_bounds__(256, 4) fused_kernel(const float* __restrict__ pred,
                                                       const float* __restrict__ gt,
                                                       float* __restrict__ out) {
    const int tid  = threadIdx.x;
    const int bid  = blockIdx.x;
    const int w    = bid >> 8;
    const int tile = (bid * 167) & (NTILE - 1);   // odd mult -> bijective swizzle
    const int tx = tile & 15, ty = tile >> 4;

    const float* __restrict__ c = w ? gt : pred;

    const float cxr = ((float)(tx * 8) + 3.5f) * STEPR;
    const float cyr = ((float)(ty * 8) + 3.5f) * STEPR;

    const int rowi = tid >> 5;          // warp = pixel row 0..7
    const int h    = tid & 31;          // lane = candidate slice
    const float gyr = (float)(ty * 8 + rowi) * STEPR;

    __shared__ float4 s_seg[NCAP];                      // 12 KB
    __shared__ float  s_inv[NCAP];                      //  3 KB
    __shared__ unsigned short s_ovf[NSEG - NCAP + 1];   // ~2.6 KB cold
    __shared__ float  s_q[64];
    __shared__ float  s_red[8];
    __shared__ int    s_cnt;
    __shared__ int    s_flag;

    if (tid == 0) s_cnt = 0;

    // ---- Phase 1a: stage 28 floats (points 8t..8t+9) via 7 LDG.128 ----
    const float4* __restrict__ c4 = (const float4*)c;
    float f[28];
#pragma unroll
    for (int q = 0; q < 7; ++q) {
        const int idx = min(6 * tid + q, 1535);  // tail clamp; seg 2047 guarded out
        const float4 v4 = __ldg(&c4[idx]);
        f[q * 4 + 0] = v4.x; f[q * 4 + 1] = v4.y;
        f[q * 4 + 2] = v4.z; f[q * 4 + 3] = v4.w;
    }

    // ---- Phase 1b: center eval in raw space ----
    float d2c[8];
    float lmin = FINF;
#pragma unroll
    for (int k = 0; k < 8; ++k) {
        const int s = 8 * tid + k;
        float d2 = FINF;
        const float pen = f[k * 3 + 2];
        const bool masked = w ? (pen != 0.0f) : (pen > 0.5f);
        if (s < NSEG && !masked) {
            const float pjx = f[k * 3 + 3];
            const float pjy = f[k * 3 + 4];
            const float vx  = f[k * 3 + 0] - pjx;
            const float vy  = f[k * 3 + 1] - pjy;
            const float vn  = vx * vx + vy * vy;
            const float inv = __fdividef(1.0f, vn);  // vn=0 -> inf; sat(NaN)=0 -> t=0 exact
            const float ux = cxr - pjx, uy = cyr - pjy;
            const float uv = fmaf(ux, vx, uy * vy);
            const float t  = satmul(uv, inv);
            const float dx = fmaf(-t, vx, ux);
            const float dy = fmaf(-t, vy, uy);
            d2 = fmaf(dy, dy, dx * dx);
        }
        d2c[k] = d2;
        lmin = fminf(lmin, d2);
    }
#pragma unroll
    for (int o = 16; o > 0; o >>= 1)
        lmin = fminf(lmin, __shfl_xor_sync(0xFFFFFFFFu, lmin, o));
    if (h == 0) s_red[rowi] = lmin;
    __syncthreads();
    float U = s_red[0];
#pragma unroll
    for (int q = 1; q < 8; ++q) U = fminf(U, s_red[q]);
    const float thd = sqrtf(U) + THR_ADD;
    const float thr = thd * thd;

    // ---- Phase 1c: survivors -> smem straight from registers ----
#pragma unroll
    for (int k = 0; k < 8; ++k) {
        if (d2c[k] < thr) {
            const int pos = atomicAdd(&s_cnt, 1);
            if (pos < NCAP) {
                const float pjx = f[k * 3 + 3];
                const float pjy = f[k * 3 + 4];
                const float vx  = f[k * 3 + 0] - pjx;
                const float vy  = f[k * 3 + 1] - pjy;
                const float vn  = vx * vx + vy * vy;
                s_seg[pos] = make_float4(pjx, pjy, vx, vy);
                s_inv[pos] = __fdividef(1.0f, vn);
            } else {
                s_ovf[pos - NCAP] = (unsigned short)(8 * tid + k);
            }
        }
    }
    __syncthreads();

    const int len = s_cnt;
    const int n1  = (len < NCAP) ? len : NCAP;
    const int npad = (n1 + 31) & ~31;   // loop bound; tail lanes clamp (re-eval last, harmless)

    // ---- Phase 2: warp=row, lane=slice; 8 px per thread per candidate ----
    float gxr[8], m[8];
#pragma unroll
    for (int k = 0; k < 8; ++k) {
        gxr[k] = (float)(tx * 8 + k) * STEPR;
        m[k]   = FINF;
    }

#define EVALROW(JJ)                                                   \
    {                                                                 \
        const int jj = min((JJ), n1 - 1);                             \
        const float4 q  = s_seg[jj];                                  \
        const float inv = s_inv[jj];                                  \
        const float uy  = gyr - q.y;                                  \
        const float cyv = uy * q.w;                                   \
        _Pragma("unroll")                                             \
        for (int k = 0; k < 8; ++k) {                                 \
            const float ux = gxr[k] - q.x;                            \
            const float uv = fmaf(ux, q.z, cyv);                      \
            const float t  = satmul(uv, inv);                         \
            const float dx = fmaf(-t, q.z, ux);                       \
            const float dy = fmaf(-t, q.w, uy);                       \
            m[k] = fminf(m[k], fmaf(dy, dy, dx * dx));                \
        }                                                             \
    }

    int j = h;
    for (; j + 32 < npad; j += 64) {
        EVALROW(j)
        EVALROW(j + 32)
    }
    for (; j < npad; j += 32) {
        EVALROW(j)
    }

    // cold overflow path (len > NCAP; not hit on this data, exact if hit)
    if (len > NCAP) {
        const int novf = len - NCAP;
        for (int o2 = 0; o2 < novf; ++o2) {
            const int s = s_ovf[o2];
            const float pjx = __ldg(&c[s * 3 + 3]);
            const float pjy = __ldg(&c[s * 3 + 4]);
            const float vx  = __ldg(&c[s * 3 + 0]) - pjx;
            const float vy  = __ldg(&c[s * 3 + 1]) - pjy;
            const float vn  = vx * vx + vy * vy;
            const float inv = __fdividef(1.0f, vn);
            const float uy  = gyr - pjy;
            const float cyv = uy * vy;
#pragma unroll
            for (int k = 0; k < 8; ++k) {
                const float ux = gxr[k] - pjx;
                const float uv = fmaf(ux, vx, cyv);
                const float t  = satmul(uv, inv);
                const float dx = fmaf(-t, vx, ux);
                const float dy = fmaf(-t, vy, uy);
                m[k] = fminf(m[k], fmaf(dy, dy, dx * dx));
            }
        }
    }

    // ---- warp shuffle-min across 32 slices, publish ----
#pragma unroll
    for (int o = 16; o > 0; o >>= 1) {
#pragma unroll
        for (int k = 0; k < 8; ++k)
            m[k] = fminf(m[k], __shfl_xor_sync(0xFFFFFFFFu, m[k], o));
    }
    const int pixbase = (ty * 8) * 128 + tx * 8;
    if (h < 8) {
        const float q = m[h];                 // pixel (rowi, h)
        s_q[rowi * 8 + h] = q;
        g_pix[w][pixbase + rowi * 128 + h] = q;
    }
    __threadfence();
    if (tid == 0) {
        const int old = atomicAdd(&g_tile_cnt[tile], 1);
        s_flag = (old == 1);
    }
    __syncthreads();

    // ---- second arriver: tile loss partial over 64 pixels ----
    if (s_flag) {
        float v = 0.0f;
        if (tid < 64) {
            const int rr = tid >> 3, cc = tid & 7;
            const float qown = s_q[tid];
            const float qoth = g_pix[w ^ 1][pixbase + rr * 128 + cc];
            const float bo = __expf(-GAMMA4 * qown);
            const float bt = __expf(-GAMMA4 * qoth);
            const float d  = bo - bt;
            v = d * d;
        }
#pragma unroll
        for (int o = 16; o > 0; o >>= 1)
            v += __shfl_xor_sync(0xFFFFFFFFu, v, o);
        if (tid == 0 || tid == 32) s_red[tid >> 5] = v;
        __syncthreads();
        if (tid == 0) {
            atomicAdd(&g_loss, s_red[0] + s_red[1]);
            __threadfence();
            const unsigned old2 = atomicAdd(&g_done, 1u);
            s_flag = (old2 == NTILE - 1) ? 2 : 0;
        }
        __syncthreads();

        // ---- last loss-CTA: finalize + reset ----
        if (s_flag == 2) {
            if (tid < NTILE) g_tile_cnt[tid] = 0;
            if (tid == 0) {
                const float total = *((volatile float*)&g_loss);
                out[0] = total * (1.0f / (float)NPIX);
                g_loss = 0.0f;
                g_done = 0u;
            }
        }
    }
}

// ---------------------------------------------------------------------------
extern "C" void kernel_launch(void* const* d_in, const int* in_sizes, int n_in,
                              void* d_out, int out_size) {
    const float* pred = (const float*)d_in[0];
    const float* gt   = (const float*)d_in[1];
    float* out = (float*)d_out;

    fused_kernel<<<512, 256>>>(pred, gt, out);
}

// round 12
// speedup vs baseline: 1.0171x; 1.0171x over previous
#include <cuda_runtime.h>
#include <math.h>

#define NSEG    2047
#define NPIX    16384
#define NTILE   256          // 16 x 16 tiles of 8x8 px
#define NHALF   1024         // segments per half
#define NCAP    640          // smem candidate capacity per half
#define GAMMA4  800.0f       // gamma * 4 (raw-space d^2 = true d^2 / 4)
#define STEPR   (1.0f / 127.0f)
// tile = 8x8 px, center (+3.5,+3.5): 2*half-diag = 7*sqrt(2) px (raw units)
#define THR_ADD (9.899495f * STEPR + 5e-4f)
#define FINF    __int_as_float(0x7F800000)

__device__ __forceinline__ float satmul(float a, float b) {
    float r; asm("mul.rn.sat.f32 %0,%1,%2;" : "=f"(r) : "f"(a), "f"(b)); return r;
}

// Cross-CTA state, reset every run by consumers (graph-replay safe).
__device__ float    g_pix2[2][2][NPIX];   // [w][half] raw-space min d^2
__device__ int      g_tile_cnt[NTILE];    // 0..4 per tile per run
__device__ float    g_loss = 0.0f;
__device__ unsigned g_done = 0;

// ---------------------------------------------------------------------------
// grid 1024 x 256: bid = half*512 + w*256 + tile (8x8 px). RAW [0,1] space.
// Phase 1: thread owns 4 contiguous segments of its HALF; 5 aligned LDG.128
//          stage 20 floats; center eval from registers; block-min U_half;
//          cull with sqrt(U_half)+2r+eps (exact: the global argmin of every
//          tile pixel survives in its own half); survivors -> smem SoA.
// Phase 2: warp = pixel row, lane = candidate slice (32); padded list,
//          8 px per thread per candidate; warp shuffle-min merge.
// Merge:   publish 64 half-mins to g_pix2[w][half]; 4th arriver per tile
//          min-combines halves, computes exp/diff^2 loss partial; 256th
//          loss-CTA writes out[0]; all counters reset for graph replay.
// ---------------------------------------------------------------------------
__global__ void __launch_bounds__(256, 4) fused_kernel(const float* __restrict__ pred,
                                                       const float* __restrict__ gt,
                                                       float* __restrict__ out) {
    const int tid  = threadIdx.x;
    const int bid  = blockIdx.x;
    const int hf   = bid >> 9;                 // segment half 0/1
    const int w    = (bid >> 8) & 1;           // transform
    const int tile = bid & (NTILE - 1);
    const int tx = tile & 15, ty = tile >> 4;

    const float* __restrict__ c = w ? gt : pred;

    const float cxr = ((float)(tx * 8) + 3.5f) * STEPR;
    const float cyr = ((float)(ty * 8) + 3.5f) * STEPR;

    const int rowi = tid >> 5;                 // warp = pixel row 0..7
    const int h    = tid & 31;                 // lane = candidate slice
    const float gyr = (float)(ty * 8 + rowi) * STEPR;

    __shared__ float4 s_seg[NCAP];                       // 10 KB
    __shared__ float  s_inv[NCAP];                       // 2.5 KB
    __shared__ unsigned short s_ovf[NHALF - NCAP + 1];   // cold
    __shared__ float  s_red[8];
    __shared__ int    s_cnt;
    __shared__ int    s_flag;

    if (tid == 0) s_cnt = 0;

    // ---- Phase 1a: stage 20 floats (points s0..s0+5) via 5 aligned LDG.128 ----
    // s0 = hf*1024 + 4*tid  ->  3*s0 divisible by 4; idx0 = 768*hf + 3*tid
    const float4* __restrict__ c4 = (const float4*)c;
    const int s0   = hf * NHALF + 4 * tid;
    const int idx0 = 768 * hf + 3 * tid;
    float f[20];
#pragma unroll
    for (int q = 0; q < 5; ++q) {
        const int idx = min(idx0 + q, 1535);   // tail clamp; seg 2047 guarded out
        const float4 v4 = __ldg(&c4[idx]);
        f[q * 4 + 0] = v4.x; f[q * 4 + 1] = v4.y;
        f[q * 4 + 2] = v4.z; f[q * 4 + 3] = v4.w;
    }

    // ---- Phase 1b: center eval in raw space ----
    float d2c[4];
    float lmin = FINF;
#pragma unroll
    for (int k = 0; k < 4; ++k) {
        const int s = s0 + k;
        float d2 = FINF;
        const float pen = f[k * 3 + 2];
        const bool masked = w ? (pen != 0.0f) : (pen > 0.5f);
        if (s < NSEG && !masked) {
            const float pjx = f[k * 3 + 3];
            const float pjy = f[k * 3 + 4];
            const float vx  = f[k * 3 + 0] - pjx;
            const float vy  = f[k * 3 + 1] - pjy;
            const float vn  = vx * vx + vy * vy;
            const float inv = __fdividef(1.0f, vn);  // vn=0 -> inf; sat(NaN)=0 -> t=0 exact
            const float ux = cxr - pjx, uy = cyr - pjy;
            const float uv = fmaf(ux, vx, uy * vy);
            const float t  = satmul(uv, inv);
            const float dx = fmaf(-t, vx, ux);
            const float dy = fmaf(-t, vy, uy);
            d2 = fmaf(dy, dy, dx * dx);
        }
        d2c[k] = d2;
        lmin = fminf(lmin, d2);
    }
#pragma unroll
    for (int o = 16; o > 0; o >>= 1)
        lmin = fminf(lmin, __shfl_xor_sync(0xFFFFFFFFu, lmin, o));
    if (h == 0) s_red[rowi] = lmin;
    __syncthreads();
    float U = s_red[0];
#pragma unroll
    for (int q = 1; q < 8; ++q) U = fminf(U, s_red[q]);
    const float thd = sqrtf(U) + THR_ADD;
    const float thr = thd * thd;

    // ---- Phase 1c: survivors -> smem straight from registers ----
#pragma unroll
    for (int k = 0; k < 4; ++k) {
        if (d2c[k] < thr) {
            const int pos = atomicAdd(&s_cnt, 1);
            if (pos < NCAP) {
                const float pjx = f[k * 3 + 3];
                const float pjy = f[k * 3 + 4];
                const float vx  = f[k * 3 + 0] - pjx;
                const float vy  = f[k * 3 + 1] - pjy;
                const float vn  = vx * vx + vy * vy;
                s_seg[pos] = make_float4(pjx, pjy, vx, vy);
                s_inv[pos] = __fdividef(1.0f, vn);
            } else {
                s_ovf[pos - NCAP] = (unsigned short)(s0 + k);
            }
        }
    }
    __syncthreads();

    // pad candidate list to a multiple of 32 with far dummies
    const int len  = s_cnt;
    const int n1   = (len < NCAP) ? len : NCAP;
    const int npad = (n1 + 31) & ~31;
    if (tid < npad - n1) {
        s_seg[n1 + tid] = make_float4(1e9f, 1e9f, 0.0f, 0.0f);
        s_inv[n1 + tid] = 0.0f;
    }
    __syncthreads();

    // ---- Phase 2: warp=row, lane=slice; 8 px per thread per candidate ----
    float gxr[8], m[8];
#pragma unroll
    for (int k = 0; k < 8; ++k) {
        gxr[k] = (float)(tx * 8 + k) * STEPR;
        m[k]   = FINF;
    }

    for (int j = h; j < npad; j += 32) {
        const float4 q  = s_seg[j];
        const float inv = s_inv[j];
        const float uy  = gyr - q.y;
        const float cyv = uy * q.w;
#pragma unroll
        for (int k = 0; k < 8; ++k) {
            const float ux = gxr[k] - q.x;
            const float uv = fmaf(ux, q.z, cyv);
            const float t  = satmul(uv, inv);
            const float dx = fmaf(-t, q.z, ux);
            const float dy = fmaf(-t, q.w, uy);
            m[k] = fminf(m[k], fmaf(dy, dy, dx * dx));
        }
    }

    // cold overflow path (len > NCAP; not hit on this data, exact if hit)
    if (len > NCAP) {
        const int novf = len - NCAP;
        for (int o2 = 0; o2 < novf; ++o2) {
            const int s = s_ovf[o2];
            const float pjx = __ldg(&c[s * 3 + 3]);
            const float pjy = __ldg(&c[s * 3 + 4]);
            const float vx  = __ldg(&c[s * 3 + 0]) - pjx;
            const float vy  = __ldg(&c[s * 3 + 1]) - pjy;
            const float vn  = vx * vx + vy * vy;
            const float inv = __fdividef(1.0f, vn);
            const float uy  = gyr - pjy;
            const float cyv = uy * vy;
#pragma unroll
            for (int k = 0; k < 8; ++k) {
                const float ux = gxr[k] - pjx;
                const float uv = fmaf(ux, vx, cyv);
                const float t  = satmul(uv, inv);
                const float dx = fmaf(-t, vx, ux);
                const float dy = fmaf(-t, vy, uy);
                m[k] = fminf(m[k], fmaf(dy, dy, dx * dx));
            }
        }
    }

    // ---- warp shuffle-min across 32 slices, publish half-mins ----
#pragma unroll
    for (int o = 16; o > 0; o >>= 1) {
#pragma unroll
        for (int k = 0; k < 8; ++k)
            m[k] = fminf(m[k], __shfl_xor_sync(0xFFFFFFFFu, m[k], o));
    }
    const int pixbase = (ty * 8) * 128 + tx * 8;
    if (h < 8)
        g_pix2[w][hf][pixbase + rowi * 128 + h] = m[h];
    __threadfence();
    if (tid == 0) {
        const int old = atomicAdd(&g_tile_cnt[tile], 1);
        s_flag = (old == 3);
    }
    __syncthreads();

    // ---- 4th arriver: combine halves, tile loss partial over 64 pixels ----
    if (s_flag) {
        __threadfence();   // acquire: order peer g_pix2 reads after counter
        float v = 0.0f;
        if (tid < 64) {
            const int pix = pixbase + (tid >> 3) * 128 + (tid & 7);
            const float q0 = fminf(g_pix2[0][0][pix], g_pix2[0][1][pix]);
            const float q1 = fminf(g_pix2[1][0][pix], g_pix2[1][1][pix]);
            const float b0 = expf(-GAMMA4 * q0);
            const float b1 = expf(-GAMMA4 * q1);
            const float d  = b0 - b1;
            v = d * d;
        }
#pragma unroll
        for (int o = 16; o > 0; o >>= 1)
            v += __shfl_xor_sync(0xFFFFFFFFu, v, o);
        if (tid == 0 || tid == 32) s_red[tid >> 5] = v;
        __syncthreads();
        if (tid == 0) {
            g_tile_cnt[tile] = 0;                  // reset for next replay
            atomicAdd(&g_loss, s_red[0] + s_red[1]);
            __threadfence();
            const unsigned old2 = atomicAdd(&g_done, 1u);
            s_flag = (old2 == NTILE - 1) ? 2 : 0;
        }
        __syncthreads();

        // ---- last loss-CTA: finalize + reset ----
        if (s_flag == 2 && tid == 0) {
            const float total = *((volatile float*)&g_loss);
            out[0] = total * (1.0f / (float)NPIX);
            g_loss = 0.0f;
            g_done = 0u;
        }
    }
}

// ---------------------------------------------------------------------------
extern "C" void kernel_launch(void* const* d_in, const int* in_sizes, int n_in,
                              void* d_out, int out_size) {
    const float* pred = (const float*)d_in[0];
    const float* gt   = (const float*)d_in[1];
    float* out = (float*)d_out;

    fused_kernel<<<1024, 256>>>(pred, gt, out);
}

// round 13
// speedup vs baseline: 1.1380x; 1.1189x over previous
#include <cuda_runtime.h>
#include <math.h>

#define NSEG    2047
#define NPIX    16384
#define NTILE   256          // 16 x 16 tiles of 8x8 px
#define NCAP    768          // smem candidate capacity
#define GAMMA4  800.0f       // gamma * 4 (raw-space d^2 = true d^2 / 4)
#define STEPR   (1.0f / 127.0f)            // raw-space grid step
// tile = 8x8 px, center (+3.5,+3.5): 2*half-diag = 7*sqrt(2) px (raw units)
#define THR_ADD (9.899495f * STEPR + 5e-4f)
#define FINF    __int_as_float(0x7F800000)

__device__ __forceinline__ float satmul(float a, float b) {
    float r; asm("mul.rn.sat.f32 %0,%1,%2;" : "=f"(r) : "f"(a), "f"(b)); return r;
}

// Cross-CTA state, reset by the last loss-CTA every run (graph-replay safe).
__device__ float    g_pix[2][NPIX];   // raw-space per-pixel min d^2
__device__ int      g_tile_cnt[NTILE];
__device__ float    g_loss = 0.0f;
__device__ unsigned g_done = 0;

// ---------------------------------------------------------------------------
// grid 512 x 256: bid = w*256 + tile (8x8 px). ALL math in RAW [0,1] space.
// Phase 1: thread owns 8 contiguous segments; 7 coalesced LDG.128 stage its
//          28 floats; center eval from registers; block-min U; exact
//          triangle-inequality cull; survivors -> s_seg/s_inv from registers.
// Phase 2: warp = pixel row (8 rows), lane = candidate slice (32); per-lane
//          loop bound (no padding, no extra barriers); 8 px per thread per
//          candidate (uy shared); warp shuffle-min merge.
// Pairing: publish 64 mins to g_pix; second arriver computes tile loss with
//          beta = exp(-800 * d2_raw); 256th loss-CTA writes out[0], resets.
// ---------------------------------------------------------------------------
__global__ void __launch_bounds__(256, 4) fused_kernel(const float* __restrict__ pred,
                                                       const float* __restrict__ gt,
                                                       float* __restrict__ out) {
    const int tid  = threadIdx.x;
    const int bid  = blockIdx.x;
    const int w    = bid >> 8;
    const int tile = bid & (NTILE - 1);
    const int tx = tile & 15, ty = tile >> 4;

    const float* __restrict__ c = w ? gt : pred;

    const float cxr = ((float)(tx * 8) + 3.5f) * STEPR;   // raw-space center
    const float cyr = ((float)(ty * 8) + 3.5f) * STEPR;

    const int rowi = tid >> 5;          // warp = pixel row 0..7
    const int h    = tid & 31;          // lane = candidate slice
    const float gyr = (float)(ty * 8 + rowi) * STEPR;

    __shared__ float4 s_seg[NCAP];                      // 12 KB
    __shared__ float  s_inv[NCAP];                      //  3 KB
    __shared__ unsigned short s_ovf[NSEG - NCAP + 1];   // ~2.6 KB cold
    __shared__ float  s_q[64];
    __shared__ float  s_red[8];
    __shared__ int    s_cnt;
    __shared__ int    s_flag;

    if (tid == 0) s_cnt = 0;

    // ---- Phase 1a: stage 28 floats (points 8t..8t+9) via 7 LDG.128 ----
    const float4* __restrict__ c4 = (const float4*)c;
    float f[28];
#pragma unroll
    for (int q = 0; q < 7; ++q) {
        int idx = 6 * tid + q;
        if (idx > 1535) idx = 1535;     // tail clamp; only affects guarded seg 2047
        const float4 v4 = __ldg(&c4[idx]);
        f[q * 4 + 0] = v4.x; f[q * 4 + 1] = v4.y;
        f[q * 4 + 2] = v4.z; f[q * 4 + 3] = v4.w;
    }

    // ---- Phase 1b: center eval in raw space ----
    float d2c[8];
    float lmin = FINF;
#pragma unroll
    for (int k = 0; k < 8; ++k) {
        const int s = 8 * tid + k;
        float d2 = FINF;
        const float pen = f[k * 3 + 2];
        const bool masked = w ? (pen != 0.0f) : (pen > 0.5f);
        if (s < NSEG && !masked) {
            const float pjx = f[k * 3 + 3];
            const float pjy = f[k * 3 + 4];
            const float vx  = f[k * 3 + 0] - pjx;
            const float vy  = f[k * 3 + 1] - pjy;
            const float vn  = vx * vx + vy * vy;
            const float inv = __fdividef(1.0f, vn);  // vn=0 -> inf; sat(NaN)=0 -> t=0 exact
            const float ux = cxr - pjx, uy = cyr - pjy;
            const float uv = fmaf(ux, vx, uy * vy);
            const float t  = satmul(uv, inv);
            const float dx = fmaf(-t, vx, ux);
            const float dy = fmaf(-t, vy, uy);
            d2 = fmaf(dy, dy, dx * dx);
        }
        d2c[k] = d2;
        lmin = fminf(lmin, d2);
    }
#pragma unroll
    for (int o = 16; o > 0; o >>= 1)
        lmin = fminf(lmin, __shfl_xor_sync(0xFFFFFFFFu, lmin, o));
    if (h == 0) s_red[rowi] = lmin;
    __syncthreads();
    float U = s_red[0];
#pragma unroll
    for (int q = 1; q < 8; ++q) U = fminf(U, s_red[q]);
    const float thd = sqrtf(U) + THR_ADD;
    const float thr = thd * thd;

    // ---- Phase 1c: survivors -> smem straight from registers ----
#pragma unroll
    for (int k = 0; k < 8; ++k) {
        if (d2c[k] < thr) {
            const int pos = atomicAdd(&s_cnt, 1);
            if (pos < NCAP) {
                const float pjx = f[k * 3 + 3];
                const float pjy = f[k * 3 + 4];
                const float vx  = f[k * 3 + 0] - pjx;
                const float vy  = f[k * 3 + 1] - pjy;
                const float vn  = vx * vx + vy * vy;
                s_seg[pos] = make_float4(pjx, pjy, vx, vy);
                s_inv[pos] = __fdividef(1.0f, vn);
            } else {
                s_ovf[pos - NCAP] = (unsigned short)(8 * tid + k);
            }
        }
    }
    __syncthreads();

    const int len = s_cnt;
    const int n1  = (len < NCAP) ? len : NCAP;

    // ---- Phase 2: warp=row, lane=slice; 8 px per thread per candidate ----
    // Per-lane loop bound: lanes past the tail simply exit earlier (branch
    // unit handles divergent trip counts); no padding, no extra barriers.
    float gxr[8], m[8];
#pragma unroll
    for (int k = 0; k < 8; ++k) {
        gxr[k] = (float)(tx * 8 + k) * STEPR;
        m[k]   = FINF;
    }

    for (int j = h; j < n1; j += 32) {
        const float4 q  = s_seg[j];
        const float inv = s_inv[j];
        const float uy  = gyr - q.y;
        const float cyv = uy * q.w;
#pragma unroll
        for (int k = 0; k < 8; ++k) {
            const float ux = gxr[k] - q.x;
            const float uv = fmaf(ux, q.z, cyv);
            const float t  = satmul(uv, inv);
            const float dx = fmaf(-t, q.z, ux);
            const float dy = fmaf(-t, q.w, uy);
            m[k] = fminf(m[k], fmaf(dy, dy, dx * dx));
        }
    }

    // cold overflow path (len > NCAP; not hit on this data, exact if hit)
    if (len > NCAP) {
        const int novf = len - NCAP;
        for (int o2 = 0; o2 < novf; ++o2) {
            const int s = s_ovf[o2];
            const float pjx = __ldg(&c[s * 3 + 3]);
            const float pjy = __ldg(&c[s * 3 + 4]);
            const float vx  = __ldg(&c[s * 3 + 0]) - pjx;
            const float vy  = __ldg(&c[s * 3 + 1]) - pjy;
            const float vn  = vx * vx + vy * vy;
            const float inv = __fdividef(1.0f, vn);
            const float uy  = gyr - pjy;
            const float cyv = uy * vy;
#pragma unroll
            for (int k = 0; k < 8; ++k) {
                const float ux = gxr[k] - pjx;
                const float uv = fmaf(ux, vx, cyv);
                const float t  = satmul(uv, inv);
                const float dx = fmaf(-t, vx, ux);
                const float dy = fmaf(-t, vy, uy);
                m[k] = fminf(m[k], fmaf(dy, dy, dx * dx));
            }
        }
    }

    // ---- warp shuffle-min across 32 slices, publish ----
#pragma unroll
    for (int o = 16; o > 0; o >>= 1) {
#pragma unroll
        for (int k = 0; k < 8; ++k)
            m[k] = fminf(m[k], __shfl_xor_sync(0xFFFFFFFFu, m[k], o));
    }
    const int pixbase = (ty * 8) * 128 + tx * 8;
    if (h < 8) {
        const float q = m[h];                 // pixel (rowi, h)
        s_q[rowi * 8 + h] = q;
        g_pix[w][pixbase + rowi * 128 + h] = q;
    }
    __threadfence();
    if (tid == 0) {
        const int old = atomicAdd(&g_tile_cnt[tile], 1);
        s_flag = (old == 1);
    }
    __syncthreads();

    // ---- second arriver: tile loss partial over 64 pixels ----
    if (s_flag) {
        float v = 0.0f;
        if (tid < 64) {
            const int rr = tid >> 3, cc = tid & 7;
            const float qown = s_q[tid];
            const float qoth = g_pix[w ^ 1][pixbase + rr * 128 + cc];
            const float bo = __expf(-GAMMA4 * qown);
            const float bt = __expf(-GAMMA4 * qoth);
            const float d  = bo - bt;
            v = d * d;
        }
#pragma unroll
        for (int o = 16; o > 0; o >>= 1)
            v += __shfl_xor_sync(0xFFFFFFFFu, v, o);
        if (tid == 0 || tid == 32) s_red[tid >> 5] = v;
        __syncthreads();
        if (tid == 0) {
            atomicAdd(&g_loss, s_red[0] + s_red[1]);
            __threadfence();
            const unsigned old2 = atomicAdd(&g_done, 1u);
            s_flag = (old2 == NTILE - 1) ? 2 : 0;
        }
        __syncthreads();

        // ---- last loss-CTA: finalize + reset ----
        if (s_flag == 2) {
            if (tid < NTILE) g_tile_cnt[tid] = 0;
            if (tid == 0) {
                const float total = *((volatile float*)&g_loss);
                out[0] = total * (1.0f / (float)NPIX);
                g_loss = 0.0f;
                g_done = 0u;
            }
        }
    }
}

// ---------------------------------------------------------------------------
extern "C" void kernel_launch(void* const* d_in, const int* in_sizes, int n_in,
                              void* d_out, int out_size) {
    const float* pred = (const float*)d_in[0];
    const float* gt   = (const float*)d_in[1];
    float* out = (float*)d_out;

    fused_kernel<<<512, 256>>>(pred, gt, out);
}

// round 14
// speedup vs baseline: 1.3333x; 1.1716x over previous
#include <cuda_runtime.h>
#include <math.h>

#define NSEG    2047
#define NPIX    16384
#define NTILE   256          // 16 x 16 tiles of 8x8 px
#define NCAP    640          // smem candidate capacity per transform
#define GAMMA4  800.0f       // gamma * 4 (raw-space d^2 = true d^2 / 4)
#define STEPR   (1.0f / 127.0f)            // raw-space grid step
// tile = 8x8 px, center (+3.5,+3.5): 2*half-diag = 7*sqrt(2) px (raw units)
#define THR_ADD (9.899495f * STEPR + 5e-4f)
#define FINF    __int_as_float(0x7F800000)

__device__ __forceinline__ float satmul(float a, float b) {
    float r; asm("mul.rn.sat.f32 %0,%1,%2;" : "=f"(r) : "f"(a), "f"(b)); return r;
}

// Cross-CTA state (graph-replay safe: reset by last CTA each run).
__device__ float    g_loss = 0.0f;
__device__ unsigned g_done = 0;

// ---------------------------------------------------------------------------
// grid 256 x 512: CTA = one 8x8-px tile, BOTH transforms.
// Threads 0-255 (warps 0-7)  handle w=0; threads 256-511 (warps 8-15) w=1.
// Each half is exactly the proven R10 structure:
//   Phase 1: 8 contiguous segs/thread, 7 coalesced LDG.128, center eval from
//            registers, per-w block-min U, exact triangle-inequality cull,
//            survivors -> s_seg[w]/s_inv[w] straight from registers.
//   Phase 2: warp = pixel row, lane = candidate slice (32), padded list,
//            8 px per thread per candidate, warp shuffle-min merge.
// Loss: both w's 64 mins meet in smem s_q -> exp/diff^2/block-sum ->
//       one atomicAdd(g_loss) per CTA; 256th CTA writes out[0], resets.
// No g_pix, no tile pairing, no threadfence-heavy tail.
// ---------------------------------------------------------------------------
__global__ void __launch_bounds__(512, 2) fused_kernel(const float* __restrict__ pred,
                                                       const float* __restrict__ gt,
                                                       float* __restrict__ out) {
    const int tid  = threadIdx.x;
    const int tile = blockIdx.x;
    const int tx = tile & 15, ty = tile >> 4;

    const int w    = tid >> 8;          // 0: pred, 1: gt (warps 0-7 / 8-15)
    const int t256 = tid & 255;
    const float* __restrict__ c = w ? gt : pred;

    const float cxr = ((float)(tx * 8) + 3.5f) * STEPR;
    const float cyr = ((float)(ty * 8) + 3.5f) * STEPR;

    const int rowi = (tid >> 5) & 7;    // warp-within-half = pixel row
    const int h    = tid & 31;          // lane = candidate slice
    const float gyr = (float)(ty * 8 + rowi) * STEPR;

    __shared__ float4 s_seg[2][NCAP];                     // 20 KB
    __shared__ float  s_inv[2][NCAP];                     //  5 KB
    __shared__ unsigned short s_ovf[2][NSEG - NCAP + 1];  // ~5.5 KB cold
    __shared__ float  s_q[2][64];
    __shared__ float  s_red[16];
    __shared__ int    s_cnt[2];

    if (tid < 2) s_cnt[tid] = 0;

    // ---- Phase 1a: stage 28 floats (points 8t..8t+9) via 7 LDG.128 ----
    const float4* __restrict__ c4 = (const float4*)c;
    float f[28];
#pragma unroll
    for (int q = 0; q < 7; ++q) {
        int idx = 6 * t256 + q;
        if (idx > 1535) idx = 1535;     // tail clamp; only affects guarded seg 2047
        const float4 v4 = __ldg(&c4[idx]);
        f[q * 4 + 0] = v4.x; f[q * 4 + 1] = v4.y;
        f[q * 4 + 2] = v4.z; f[q * 4 + 3] = v4.w;
    }

    // ---- Phase 1b: center eval in raw space ----
    float d2c[8];
    float lmin = FINF;
#pragma unroll
    for (int k = 0; k < 8; ++k) {
        const int s = 8 * t256 + k;
        float d2 = FINF;
        const float pen = f[k * 3 + 2];
        const bool masked = w ? (pen != 0.0f) : (pen > 0.5f);
        if (s < NSEG && !masked) {
            const float pjx = f[k * 3 + 3];
            const float pjy = f[k * 3 + 4];
            const float vx  = f[k * 3 + 0] - pjx;
            const float vy  = f[k * 3 + 1] - pjy;
            const float vn  = vx * vx + vy * vy;
            const float inv = __fdividef(1.0f, vn);  // vn=0 -> inf; sat(NaN)=0 -> t=0 exact
            const float ux = cxr - pjx, uy = cyr - pjy;
            const float uv = fmaf(ux, vx, uy * vy);
            const float t  = satmul(uv, inv);
            const float dx = fmaf(-t, vx, ux);
            const float dy = fmaf(-t, vy, uy);
            d2 = fmaf(dy, dy, dx * dx);
        }
        d2c[k] = d2;
        lmin = fminf(lmin, d2);
    }
#pragma unroll
    for (int o = 16; o > 0; o >>= 1)
        lmin = fminf(lmin, __shfl_xor_sync(0xFFFFFFFFu, lmin, o));
    if (h == 0) s_red[tid >> 5] = lmin;
    __syncthreads();                                   // #1
    const int ubase = w * 8;
    float U = s_red[ubase];
#pragma unroll
    for (int q = 1; q < 8; ++q) U = fminf(U, s_red[ubase + q]);
    const float thd = sqrtf(U) + THR_ADD;
    const float thr = thd * thd;

    // ---- Phase 1c: survivors -> smem straight from registers ----
#pragma unroll
    for (int k = 0; k < 8; ++k) {
        if (d2c[k] < thr) {
            const int pos = atomicAdd(&s_cnt[w], 1);
            if (pos < NCAP) {
                const float pjx = f[k * 3 + 3];
                const float pjy = f[k * 3 + 4];
                const float vx  = f[k * 3 + 0] - pjx;
                const float vy  = f[k * 3 + 1] - pjy;
                const float vn  = vx * vx + vy * vy;
                s_seg[w][pos] = make_float4(pjx, pjy, vx, vy);
                s_inv[w][pos] = __fdividef(1.0f, vn);
            } else {
                s_ovf[w][pos - NCAP] = (unsigned short)(8 * t256 + k);
            }
        }
    }
    __syncthreads();                                   // #2

    // pad this w's candidate list to a multiple of 32 with far dummies
    const int len  = s_cnt[w];
    const int n1   = (len < NCAP) ? len : NCAP;
    const int npad = (n1 + 31) & ~31;
    if (t256 < npad - n1) {
        s_seg[w][n1 + t256] = make_float4(1e9f, 1e9f, 0.0f, 0.0f);
        s_inv[w][n1 + t256] = 0.0f;
    }
    __syncthreads();                                   // #3

    // ---- Phase 2: warp=row, lane=slice; 8 px per thread per candidate ----
    float gxr[8], m[8];
#pragma unroll
    for (int k = 0; k < 8; ++k) {
        gxr[k] = (float)(tx * 8 + k) * STEPR;
        m[k]   = FINF;
    }

    for (int j = h; j < npad; j += 32) {
        const float4 q  = s_seg[w][j];
        const float inv = s_inv[w][j];
        const float uy  = gyr - q.y;
        const float cyv = uy * q.w;
#pragma unroll
        for (int k = 0; k < 8; ++k) {
            const float ux = gxr[k] - q.x;
            const float uv = fmaf(ux, q.z, cyv);
            const float t  = satmul(uv, inv);
            const float dx = fmaf(-t, q.z, ux);
            const float dy = fmaf(-t, q.w, uy);
            m[k] = fminf(m[k], fmaf(dy, dy, dx * dx));
        }
    }

    // cold overflow path (len > NCAP; not hit on this data, exact if hit)
    if (len > NCAP) {
        const int novf = len - NCAP;
        for (int o2 = 0; o2 < novf; ++o2) {
            const int s = s_ovf[w][o2];
            const float pjx = __ldg(&c[s * 3 + 3]);
            const float pjy = __ldg(&c[s * 3 + 4]);
            const float vx  = __ldg(&c[s * 3 + 0]) - pjx;
            const float vy  = __ldg(&c[s * 3 + 1]) - pjy;
            const float vn  = vx * vx + vy * vy;
            const float inv = __fdividef(1.0f, vn);
            const float uy  = gyr - pjy;
            const float cyv = uy * vy;
#pragma unroll
            for (int k = 0; k < 8; ++k) {
                const float ux = gxr[k] - pjx;
                const float uv = fmaf(ux, vx, cyv);
                const float t  = satmul(uv, inv);
                const float dx = fmaf(-t, vx, ux);
                const float dy = fmaf(-t, vy, uy);
                m[k] = fminf(m[k], fmaf(dy, dy, dx * dx));
            }
        }
    }

    // ---- warp shuffle-min across 32 slices ----
#pragma unroll
    for (int o = 16; o > 0; o >>= 1) {
#pragma unroll
        for (int k = 0; k < 8; ++k)
            m[k] = fminf(m[k], __shfl_xor_sync(0xFFFFFFFFu, m[k], o));
    }
    if (h < 8)
        s_q[w][rowi * 8 + h] = m[h];    // pixel (rowi, h) of transform w
    __syncthreads();                                   // #4

    // ---- loss over the tile's 64 pixels (both transforms now in smem) ----
    float v = 0.0f;
    if (tid < 64) {
        const float b0 = __expf(-GAMMA4 * s_q[0][tid]);
        const float b1 = __expf(-GAMMA4 * s_q[1][tid]);
        const float d  = b0 - b1;
        v = d * d;
    }
#pragma unroll
    for (int o = 16; o > 0; o >>= 1)
        v += __shfl_xor_sync(0xFFFFFFFFu, v, o);
    if (tid == 0 || tid == 32) s_red[tid >> 5] = v;
    __syncthreads();                                   // #5

    if (tid == 0) {
        atomicAdd(&g_loss, s_red[0] + s_red[1]);
        __threadfence();
        const unsigned old = atomicAdd(&g_done, 1u);
        if (old == NTILE - 1) {
            const float total = *((volatile float*)&g_loss);
            out[0] = total * (1.0f / (float)NPIX);
            g_loss = 0.0f;
            g_done = 0u;
        }
    }
}

// ---------------------------------------------------------------------------
extern "C" void kernel_launch(void* const* d_in, const int* in_sizes, int n_in,
                              void* d_out, int out_size) {
    const float* pred = (const float*)d_in[0];
    const float* gt   = (const float*)d_in[1];
    float* out = (float*)d_out;

    fused_kernel<<<NTILE, 512>>>(pred, gt, out);
}

// round 15
// speedup vs baseline: 1.3434x; 1.0075x over previous
#include <cuda_runtime.h>
#include <math.h>

#define NSEG    2047
#define NPIX    16384
#define NTILE   256          // 16 x 16 tiles of 8x8 px
#define NCAP    640          // smem candidate capacity per transform
#define GAMMA4  800.0f       // gamma * 4 (raw-space d^2 = true d^2 / 4)
#define STEPR   (1.0f / 127.0f)            // raw-space grid step
// tile = 8x8 px, center (+3.5,+3.5): 2*half-diag = 7*sqrt(2) px (raw units)
#define THR_ADD (9.899495f * STEPR + 5e-4f)
#define FINF    __int_as_float(0x7F800000)

__device__ __forceinline__ float satmul(float a, float b) {
    float r; asm("mul.rn.sat.f32 %0,%1,%2;" : "=f"(r) : "f"(a), "f"(b)); return r;
}
// half-private barrier: 256 threads of one w-half (ids 1 and 2)
__device__ __forceinline__ void half_bar(int w) {
    asm volatile("bar.sync %0, 256;" :: "r"(w + 1) : "memory");
}

// Cross-CTA state (graph-replay safe: reset by last CTA each run).
__device__ float    g_loss = 0.0f;
__device__ unsigned g_done = 0;

// ---------------------------------------------------------------------------
// grid 256 x 512: CTA = one 8x8-px tile, BOTH transforms.
// Threads 0-255 (warps 0-7) handle w=0; 256-511 (warps 8-15) handle w=1.
// Phases 1-2 are half-private -> synced with NAMED barriers (bar.sync w+1,256)
// so the two halves never stall each other; only the pre-loss barrier is
// full-block. Loss computed by warp 0 alone (2 px/lane), one atomicAdd/CTA.
// ---------------------------------------------------------------------------
__global__ void __launch_bounds__(512, 2) fused_kernel(const float* __restrict__ pred,
                                                       const float* __restrict__ gt,
                                                       float* __restrict__ out) {
    const int tid  = threadIdx.x;
    const int tile = blockIdx.x;
    const int tx = tile & 15, ty = tile >> 4;

    const int w    = tid >> 8;          // 0: pred, 1: gt
    const int t256 = tid & 255;
    const float* __restrict__ c = w ? gt : pred;

    const float cxr = ((float)(tx * 8) + 3.5f) * STEPR;
    const float cyr = ((float)(ty * 8) + 3.5f) * STEPR;

    const int rowi = (tid >> 5) & 7;    // warp-within-half = pixel row
    const int h    = tid & 31;          // lane = candidate slice
    const float gyr = (float)(ty * 8 + rowi) * STEPR;

    __shared__ float4 s_seg[2][NCAP];                     // 20 KB
    __shared__ float  s_inv[2][NCAP];                     //  5 KB
    __shared__ unsigned short s_ovf[2][NSEG - NCAP + 1];  // ~5.5 KB cold
    __shared__ float  s_q[2][64];
    __shared__ float  s_red[16];
    __shared__ int    s_cnt[2];

    if (t256 == 0) s_cnt[w] = 0;        // each half resets its own counter

    // ---- Phase 1a: stage 28 floats (points 8t..8t+9) via 7 LDG.128 ----
    const float4* __restrict__ c4 = (const float4*)c;
    float f[28];
#pragma unroll
    for (int q = 0; q < 7; ++q) {
        int idx = 6 * t256 + q;
        if (idx > 1535) idx = 1535;     // tail clamp; only affects guarded seg 2047
        const float4 v4 = __ldg(&c4[idx]);
        f[q * 4 + 0] = v4.x; f[q * 4 + 1] = v4.y;
        f[q * 4 + 2] = v4.z; f[q * 4 + 3] = v4.w;
    }

    // ---- Phase 1b: center eval in raw space ----
    float d2c[8];
    float lmin = FINF;
#pragma unroll
    for (int k = 0; k < 8; ++k) {
        const int s = 8 * t256 + k;
        float d2 = FINF;
        const float pen = f[k * 3 + 2];
        const bool masked = w ? (pen != 0.0f) : (pen > 0.5f);
        if (s < NSEG && !masked) {
            const float pjx = f[k * 3 + 3];
            const float pjy = f[k * 3 + 4];
            const float vx  = f[k * 3 + 0] - pjx;
            const float vy  = f[k * 3 + 1] - pjy;
            const float vn  = vx * vx + vy * vy;
            const float inv = __fdividef(1.0f, vn);  // vn=0 -> inf; sat(NaN)=0 -> t=0 exact
            const float ux = cxr - pjx, uy = cyr - pjy;
            const float uv = fmaf(ux, vx, uy * vy);
            const float t  = satmul(uv, inv);
            const float dx = fmaf(-t, vx, ux);
            const float dy = fmaf(-t, vy, uy);
            d2 = fmaf(dy, dy, dx * dx);
        }
        d2c[k] = d2;
        lmin = fminf(lmin, d2);
    }
#pragma unroll
    for (int o = 16; o > 0; o >>= 1)
        lmin = fminf(lmin, __shfl_xor_sync(0xFFFFFFFFu, lmin, o));
    if (h == 0) s_red[tid >> 5] = lmin;
    half_bar(w);                                        // #1 (half-private)
    const int ubase = w * 8;
    float U = s_red[ubase];
#pragma unroll
    for (int q = 1; q < 8; ++q) U = fminf(U, s_red[ubase + q]);
    const float thd = sqrtf(U) + THR_ADD;
    const float thr = thd * thd;

    // ---- Phase 1c: survivors -> smem straight from registers ----
#pragma unroll
    for (int k = 0; k < 8; ++k) {
        if (d2c[k] < thr) {
            const int pos = atomicAdd(&s_cnt[w], 1);
            if (pos < NCAP) {
                const float pjx = f[k * 3 + 3];
                const float pjy = f[k * 3 + 4];
                const float vx  = f[k * 3 + 0] - pjx;
                const float vy  = f[k * 3 + 1] - pjy;
                const float vn  = vx * vx + vy * vy;
                s_seg[w][pos] = make_float4(pjx, pjy, vx, vy);
                s_inv[w][pos] = __fdividef(1.0f, vn);
            } else {
                s_ovf[w][pos - NCAP] = (unsigned short)(8 * t256 + k);
            }
        }
    }
    half_bar(w);                                        // #2 (half-private)

    // pad this w's candidate list to a multiple of 32 with far dummies
    const int len  = s_cnt[w];
    const int n1   = (len < NCAP) ? len : NCAP;
    const int npad = (n1 + 31) & ~31;
    if (t256 < npad - n1) {
        s_seg[w][n1 + t256] = make_float4(1e9f, 1e9f, 0.0f, 0.0f);
        s_inv[w][n1 + t256] = 0.0f;
    }
    half_bar(w);                                        // #3 (half-private)

    // ---- Phase 2: warp=row, lane=slice; 8 px per thread per candidate ----
    float gxr[8], m[8];
#pragma unroll
    for (int k = 0; k < 8; ++k) {
        gxr[k] = (float)(tx * 8 + k) * STEPR;
        m[k]   = FINF;
    }

    for (int j = h; j < npad; j += 32) {
        const float4 q  = s_seg[w][j];
        const float inv = s_inv[w][j];
        const float uy  = gyr - q.y;
        const float cyv = uy * q.w;
#pragma unroll
        for (int k = 0; k < 8; ++k) {
            const float ux = gxr[k] - q.x;
            const float uv = fmaf(ux, q.z, cyv);
            const float t  = satmul(uv, inv);
            const float dx = fmaf(-t, q.z, ux);
            const float dy = fmaf(-t, q.w, uy);
            m[k] = fminf(m[k], fmaf(dy, dy, dx * dx));
        }
    }

    // cold overflow path (len > NCAP; not hit on this data, exact if hit)
    if (len > NCAP) {
        const int novf = len - NCAP;
        for (int o2 = 0; o2 < novf; ++o2) {
            const int s = s_ovf[w][o2];
            const float pjx = __ldg(&c[s * 3 + 3]);
            const float pjy = __ldg(&c[s * 3 + 4]);
            const float vx  = __ldg(&c[s * 3 + 0]) - pjx;
            const float vy  = __ldg(&c[s * 3 + 1]) - pjy;
            const float vn  = vx * vx + vy * vy;
            const float inv = __fdividef(1.0f, vn);
            const float uy  = gyr - pjy;
            const float cyv = uy * vy;
#pragma unroll
            for (int k = 0; k < 8; ++k) {
                const float ux = gxr[k] - pjx;
                const float uv = fmaf(ux, vx, cyv);
                const float t  = satmul(uv, inv);
                const float dx = fmaf(-t, vx, ux);
                const float dy = fmaf(-t, vy, uy);
                m[k] = fminf(m[k], fmaf(dy, dy, dx * dx));
            }
        }
    }

    // ---- warp shuffle-min across 32 slices ----
#pragma unroll
    for (int o = 16; o > 0; o >>= 1) {
#pragma unroll
        for (int k = 0; k < 8; ++k)
            m[k] = fminf(m[k], __shfl_xor_sync(0xFFFFFFFFu, m[k], o));
    }
    if (h < 8)
        s_q[w][rowi * 8 + h] = m[h];    // pixel (rowi, h) of transform w
    __syncthreads();                    // full-block: loss reads both halves

    // ---- loss over 64 pixels, warp 0 only (2 px/lane), one atomicAdd ----
    if (tid < 32) {
        const float b0a = __expf(-GAMMA4 * s_q[0][tid]);
        const float b1a = __expf(-GAMMA4 * s_q[1][tid]);
        const float b0b = __expf(-GAMMA4 * s_q[0][tid + 32]);
        const float b1b = __expf(-GAMMA4 * s_q[1][tid + 32]);
        const float da = b0a - b1a;
        const float db = b0b - b1b;
        float v = fmaf(da, da, db * db);
#pragma unroll
        for (int o = 16; o > 0; o >>= 1)
            v += __shfl_xor_sync(0xFFFFFFFFu, v, o);
        if (tid == 0) {
            atomicAdd(&g_loss, v);
            __threadfence();
            const unsigned old = atomicAdd(&g_done, 1u);
            if (old == NTILE - 1) {
                const float total = *((volatile float*)&g_loss);
                out[0] = total * (1.0f / (float)NPIX);
                g_loss = 0.0f;
                g_done = 0u;
            }
        }
    }
}

// ---------------------------------------------------------------------------
extern "C" void kernel_launch(void* const* d_in, const int* in_sizes, int n_in,
                              void* d_out, int out_size) {
    const float* pred = (const float*)d_in[0];
    const float* gt   = (const float*)d_in[1];
    float* out = (float*)d_out;

    fused_kernel<<<NTILE, 512>>>(pred, gt, out);
}